// round 14
// baseline (speedup 1.0000x reference)
#include <cuda_runtime.h>
#include <cstdint>

#define B_   8
#define NQ_  75
#define NS_  5
#define NG_  4
#define NF_  49
#define C_   64

#define STR_  68            // floats per row (8B aligned)
#define H_    34            // u64 per row
#define XROWS_ 296          // 245 support + 49 query + 2 pad
#define NT2_  544           // 74 i-tiles x 7 j-tiles = 518 active
#define NV_   5             // queries per block
#define GRID2_ 480          // 32 (b,g) x 15 chunks

#define NEG_L2E8  (-0.18033688011112042f)
#define POS_L2E4  ( 0.36067376022224084f)

// smem float offsets (k2)
#define O_XS    0
#define O_RSQ   (XROWS_ * STR_)          // 20128
#define O_BET   (O_RSQ + 296)
#define O_GAM   (O_BET + 248)
#define O_SCRR  (O_GAM + 248)            // 245*7
#define O_SCRQ  (O_SCRR + 1715)          // 245*7
#define O_S2    (O_SCRQ + 1715)          // 245
#define O_SQ2   (O_S2 + 245)             // 245
#define O_RED   (O_SQ2 + 245)            // 16
#define SM2_FLOATS (O_RED + 16)

__device__ float g_p1[B_ * NQ_ * NS_ * NG_];
__device__ float g_p2[B_ * NQ_ * NS_ * NG_];
__device__ float g_kss[B_ * NS_ * NG_ * NF_ * NF_];

__device__ __forceinline__ void fma2(unsigned long long& d,
                                     unsigned long long a, unsigned long long b) {
    asm("fma.rn.f32x2 %0, %1, %2, %0;" : "+l"(d) : "l"(a), "l"(b));
}
__device__ __forceinline__ float f32x2_sum(unsigned long long v) {
    return __uint_as_float((unsigned)v) + __uint_as_float((unsigned)(v >> 32));
}
__device__ __forceinline__ float mg_from_arg(float arg) {
    float t;
    asm("ex2.approx.f32 %0, %1;" : "=f"(t) : "f"(arg));
    float t2 = t * t;
    float s1 = fmaf(t, t, t);
    float t4 = t2 * t2;
    float t8 = t4 * t4;
    float s2 = fmaf(t8, t8, t8);
    return (s1 + t4) + s2;
}

// ---------------------------------------------------------------------------
// k1a: per (b,s,g) -> Kss (49x49) -> g_kss. 13x13 grid of 4x4 tiles.
// ---------------------------------------------------------------------------
__global__ __launch_bounds__(192) void k1a_kss(const float* __restrict__ sup) {
    __shared__ float xs[52 * STR_];
    __shared__ float ssq[52];

    int bid = blockIdx.x;
    int tid = threadIdx.x;

    const float* sb = sup + (size_t)bid * 49 * 64;
    for (int idx = tid; idx < 52 * 16; idx += 192) {
        int r = idx >> 4, c4 = idx & 15;
        float4 v = make_float4(0.f, 0.f, 0.f, 0.f);
        if (r < 49) v = *(const float4*)(sb + r * 64 + c4 * 4);
        *(float4*)(xs + r * STR_ + c4 * 4) = v;
    }
    __syncthreads();

    if (tid < 52) {
        const float2* xr = (const float2*)(xs + tid * STR_);
        float a0 = 0.f, a1 = 0.f;
        #pragma unroll
        for (int c = 0; c < 32; c++) { float2 x = xr[c]; a0 = fmaf(x.x, x.x, a0); a1 = fmaf(x.y, x.y, a1); }
        ssq[tid] = NEG_L2E8 * (a0 + a1);
    }
    __syncthreads();

    if (tid < 169) {
        int it = tid / 13, jt = tid - it * 13;
        float acc[16];
        #pragma unroll
        for (int k = 0; k < 16; k++) acc[k] = 0.f;
        const float2* A  = (const float2*)(xs + it * 4 * STR_);
        const float2* Bm = (const float2*)(xs + jt * 4 * STR_);
        #pragma unroll 2
        for (int c2 = 0; c2 < 32; c2++) {
            float2 a[4], bb[4];
            #pragma unroll
            for (int k = 0; k < 4; k++) a[k]  = A[k * H_ + c2];
            #pragma unroll
            for (int k = 0; k < 4; k++) bb[k] = Bm[k * H_ + c2];
            #pragma unroll
            for (int ii = 0; ii < 4; ii++)
                #pragma unroll
                for (int jj = 0; jj < 4; jj++) {
                    acc[ii * 4 + jj] = fmaf(a[ii].x, bb[jj].x, acc[ii * 4 + jj]);
                    acc[ii * 4 + jj] = fmaf(a[ii].y, bb[jj].y, acc[ii * 4 + jj]);
                }
        }
        float* kout = g_kss + (size_t)bid * 2401;
        #pragma unroll
        for (int ii = 0; ii < 4; ii++) {
            int i = it * 4 + ii;
            if (i < 49) {
                float ai = ssq[i];
                #pragma unroll
                for (int jj = 0; jj < 4; jj++) {
                    int j = jt * 4 + jj;
                    if (j < 49) {
                        float arg = fmaf(POS_L2E4, acc[ii * 4 + jj], ai + ssq[j]);
                        kout[i * 49 + j] = mg_from_arg(arg);
                    }
                }
            }
        }
    }
}

// ---------------------------------------------------------------------------
// k1b: per (b,s,g,vchunk of 15) -> beta^T Kss beta (Kss L2-hot)
// ---------------------------------------------------------------------------
__global__ __launch_bounds__(256) void k1b_bilinear(const float* __restrict__ beta) {
    __shared__ float kss[49 * 50];
    __shared__ float betas[15 * 50];
    __shared__ float scr[735];

    int bid = blockIdx.x;
    int g = bid & 3;
    int rest = bid >> 2;
    int s = rest % NS_;  rest /= NS_;
    int vt = rest % 5;
    int b = rest / 5;
    int tid = threadIdx.x;

    int bid160 = (b * NS_ + s) * NG_ + g;
    const float* ksrc = g_kss + (size_t)bid160 * 2401;
    for (int idx = tid; idx < 2401; idx += 256) {
        int i = idx / 49, j = idx - i * 49;
        kss[i * 50 + j] = ksrc[idx];
    }
    for (int idx = tid; idx < 15 * 49; idx += 256) {
        int vv = idx / 49, j = idx - vv * 49;
        int v = vt * 15 + vv;
        size_t off = ((size_t)((b * NQ_ + v) * NS_ + s) * NG_ + g) * 49 + j;
        betas[vv * 50 + j] = beta[off];
    }
    __syncthreads();

    for (int t = tid; t < 735; t += 256) {
        int vv = t / 49, i = t - vv * 49;
        const float2* kr = (const float2*)(kss + i * 50);
        const float2* bv = (const float2*)(betas + vv * 50);
        float r0 = 0.f, r1 = 0.f;
        #pragma unroll
        for (int c = 0; c < 24; c++) {
            float2 kk = kr[c], bb = bv[c];
            r0 = fmaf(kk.x, bb.x, r0);
            r1 = fmaf(kk.y, bb.y, r1);
        }
        float r = r0 + r1 + kss[i * 50 + 48] * betas[vv * 50 + 48];
        scr[t] = betas[vv * 50 + i] * r;
    }
    __syncthreads();

    if (tid < 15) {
        float acc = 0.f;
        #pragma unroll
        for (int k = 0; k < 49; k++) acc += scr[tid * 49 + k];
        int v = vt * 15 + tid;
        g_p1[((b * NQ_ + v) * NS_ + s) * NG_ + g] = acc;
    }
}

// ---------------------------------------------------------------------------
// k2: per (b,g,vchunk of 5). Support tile resident across 5 queries.
// Dots via packed fma.rn.f32x2 4x7 micro-tiles (74x7 grid, 518/544 threads).
// ---------------------------------------------------------------------------
__global__ __launch_bounds__(NT2_, 1) void k2_main(const float* __restrict__ sup,
                                                   const float* __restrict__ qry,
                                                   const float* __restrict__ beta,
                                                   const float* __restrict__ gamma) {
    extern __shared__ float sm[];
    float* xs   = sm + O_XS;
    float* rsq  = sm + O_RSQ;
    float* bet  = sm + O_BET;
    float* gam  = sm + O_GAM;
    float* scrR = sm + O_SCRR;
    float* scrQ = sm + O_SCRQ;
    float* s2   = sm + O_S2;
    float* sq2  = sm + O_SQ2;
    float* red  = sm + O_RED;

    int bid = blockIdx.x;             // 0..479
    int bg = bid / 15;                // b*4+g
    int chunk = bid - bg * 15;
    int b = bg >> 2;
    int g = bg & 3;
    int tid = threadIdx.x;

    // ---- support tile (resident) + pad rows ----
    const float* supb = sup + (size_t)(b * (NS_ * NG_) + g) * 49 * 64;  // + s*4*3136
    for (int idx = tid; idx < 245 * 16; idx += NT2_) {
        int r = idx >> 4, c4 = idx & 15;
        int s = r / 49, i = r - s * 49;
        float4 v = *(const float4*)(supb + (size_t)s * (NG_ * 49 * 64) + i * 64 + c4 * 4);
        *(float4*)(xs + r * STR_ + c4 * 4) = v;
    }
    if (tid < 32) {   // zero pad rows 294,295
        int r = 294 + (tid >> 4), c4 = tid & 15;
        *(float4*)(xs + r * STR_ + c4 * 4) = make_float4(0.f, 0.f, 0.f, 0.f);
    }
    __syncthreads();
    for (int r = tid; r < 245; r += NT2_) {
        const float2* xr = (const float2*)(xs + r * STR_);
        float a0 = 0.f, a1 = 0.f;
        #pragma unroll
        for (int c = 0; c < 32; c++) { float2 x = xr[c]; a0 = fmaf(x.x, x.x, a0); a1 = fmaf(x.y, x.y, a1); }
        rsq[r] = NEG_L2E8 * (a0 + a1);
    }
    if (tid < 2) rsq[294 + tid] = 0.f;

    bool active = (tid < 518);
    int it = tid / 7;                 // 0..73
    int jt = tid - it * 7;            // 0..6

    for (int iv = 0; iv < NV_; iv++) {
        int v = chunk * NV_ + iv;
        const float* qryb = qry + ((size_t)(b * NQ_ + v) * NG_ + g) * 49 * 64;

        // query rows + bet/gam
        for (int idx = tid; idx < 49 * 16; idx += NT2_) {
            int r = idx >> 4, c4 = idx & 15;
            *(float4*)(xs + (245 + r) * STR_ + c4 * 4) = *(const float4*)(qryb + r * 64 + c4 * 4);
        }
        for (int idx = tid; idx < NS_ * 49; idx += NT2_) {
            int s = idx / 49, j = idx - s * 49;
            size_t off = ((size_t)((b * NQ_ + v) * NS_ + s) * NG_ + g) * 49 + j;
            bet[idx] = beta[off];
            gam[idx] = gamma[off];
        }
        __syncthreads();

        if (tid < 49) {
            const float2* xr = (const float2*)(xs + (245 + tid) * STR_);
            float a0 = 0.f, a1 = 0.f;
            #pragma unroll
            for (int c = 0; c < 32; c++) { float2 x = xr[c]; a0 = fmaf(x.x, x.x, a0); a1 = fmaf(x.y, x.y, a1); }
            rsq[245 + tid] = NEG_L2E8 * (a0 + a1);
        }
        __syncthreads();

        if (active) {
            unsigned long long acc2[28];
            #pragma unroll
            for (int k = 0; k < 28; k++) acc2[k] = 0ull;

            const unsigned long long* A  = (const unsigned long long*)(xs + it * 4 * STR_);
            const unsigned long long* Bq = (const unsigned long long*)(xs + (245 + jt * 7) * STR_);
            #pragma unroll 1
            for (int c2 = 0; c2 < 32; c2++) {
                unsigned long long a2[4], b2[7];
                #pragma unroll
                for (int k = 0; k < 4; k++) a2[k] = A[k * H_ + c2];
                #pragma unroll
                for (int k = 0; k < 7; k++) b2[k] = Bq[k * H_ + c2];
                #pragma unroll
                for (int ii = 0; ii < 4; ii++)
                    #pragma unroll
                    for (int jj = 0; jj < 7; jj++)
                        fma2(acc2[ii * 7 + jj], a2[ii], b2[jj]);
            }

            float qsq[7];
            int jbase = jt * 7;
            #pragma unroll
            for (int jj = 0; jj < 7; jj++) qsq[jj] = rsq[245 + jbase + jj];

            int i0 = it * 4;
            #pragma unroll
            for (int ii = 0; ii < 4; ii++) {
                int i = i0 + ii;
                if (i < 294) {
                    float ai = rsq[i];
                    float kv[7];
                    #pragma unroll
                    for (int jj = 0; jj < 7; jj++) {
                        float dot = f32x2_sum(acc2[ii * 7 + jj]);
                        kv[jj] = mg_from_arg(fmaf(POS_L2E4, dot, ai + qsq[jj]));
                    }
                    if (i < 245) {
                        int s = i / 49;
                        const float* gs = gam + s * 49 + jbase;
                        float rowsum = 0.f;
                        #pragma unroll
                        for (int jj = 0; jj < 7; jj++) rowsum = fmaf(kv[jj], gs[jj], rowsum);
                        scrR[i * 7 + jt] = bet[i] * rowsum;
                    } else {
                        int q = i - 245;
                        #pragma unroll
                        for (int s = 0; s < 5; s++) {
                            const float* gs = gam + s * 49;
                            float rowsum = 0.f;
                            #pragma unroll
                            for (int jj = 0; jj < 7; jj++) rowsum = fmaf(kv[jj], gs[jbase + jj], rowsum);
                            scrQ[(s * 49 + q) * 7 + jt] = gs[q] * rowsum;
                        }
                    }
                }
            }
        }
        __syncthreads();

        // reduce stage 1: 490 threads sum 7 each
        if (tid < 245) {
            const float* src = scrR + tid * 7;
            s2[tid] = ((src[0] + src[1]) + (src[2] + src[3])) + ((src[4] + src[5]) + src[6]);
        } else if (tid < 490) {
            const float* src = scrQ + (tid - 245) * 7;
            sq2[tid - 245] = ((src[0] + src[1]) + (src[2] + src[3])) + ((src[4] + src[5]) + src[6]);
        }
        __syncthreads();

        if (tid < 10) {
            int s = tid % 5;
            const float* src = (tid < 5) ? (s2 + s * 49) : (sq2 + s * 49);
            float acc = 0.f;
            #pragma unroll
            for (int k = 0; k < 49; k++) acc += src[k];
            red[tid] = acc;
        }
        __syncthreads();

        if (tid < NS_) {
            int idx = ((b * NQ_ + v) * NS_ + tid) * NG_ + g;
            g_p2[idx] = red[5 + tid] - 2.0f * red[tid];
        }
        __syncthreads();
    }
}

__global__ void k3_reduce(float* __restrict__ out) {
    int o = blockIdx.x * blockDim.x + threadIdx.x;
    if (o < B_ * NQ_ * NS_) {
        float s = 0.0f;
        #pragma unroll
        for (int g = 0; g < NG_; g++) s += g_p1[o * NG_ + g] + g_p2[o * NG_ + g];
        out[o] = 0.25f * s;
    }
}

extern "C" void kernel_launch(void* const* d_in, const int* in_sizes, int n_in,
                              void* d_out, int out_size) {
    const float* sup   = (const float*)d_in[0];
    const float* qry   = (const float*)d_in[1];
    const float* beta  = (const float*)d_in[2];
    const float* gamma = (const float*)d_in[3];
    float* out = (float*)d_out;

    const int smem2 = SM2_FLOATS * (int)sizeof(float);
    static bool configured = false;
    if (!configured) {
        cudaFuncSetAttribute(k2_main, cudaFuncAttributeMaxDynamicSharedMemorySize, smem2);
        configured = true;
    }

    k1a_kss<<<B_ * NS_ * NG_, 192>>>(sup);
    k1b_bilinear<<<B_ * NS_ * NG_ * 5, 256>>>(beta);
    k2_main<<<GRID2_, NT2_, smem2>>>(sup, qry, beta, gamma);
    k3_reduce<<<(B_ * NQ_ * NS_ + 255) / 256, 256>>>(out);
}

// round 15
// speedup vs baseline: 1.4138x; 1.4138x over previous
#include <cuda_runtime.h>
#include <cuda_bf16.h>
#include <cstdint>

#define B_   8
#define NQ_  75
#define NS_  5
#define NG_  4
#define NF_  49
#define C_   64

#define STR_  68
#define NT2_  384

#define NEG_L2E8  (-0.18033688011112042f)
#define POS_L2E4  ( 0.36067376022224084f)

// ---- k2 smem layout (bytes / floats) ----
#define O_AHI   0                 // 320*128 bf16 tile
#define O_BHI   40960             // 64*128
#define FBASE_  49152
#define F_RSQ   0                 // 320 (scaled by NEG_L2E8; pad rows 0)
#define F_BET   320               // 248
#define F_GAM   568               // 248
#define F_SCR   816               // 248
#define F_SCRQ  1064              // 248
#define F_SCR4  1312              // 980
#define F_SCRQ4 2292              // 980
#define F_RED   3272              // 16
#define F_SQP   3288              // 320*16
#define SM2_BYTES (FBASE_ + (F_SQP + 5120) * 4)

__device__ float g_p1[B_ * NQ_ * NS_ * NG_];
__device__ float g_p2[B_ * NQ_ * NS_ * NG_];
__device__ float g_kss[B_ * NS_ * NG_ * NF_ * NF_];

__device__ __forceinline__ uint32_t smem_u32(const void* p) {
    uint32_t a;
    asm("{ .reg .u64 t; cvta.to.shared.u64 t, %1; cvt.u32.u64 %0, t; }" : "=r"(a) : "l"(p));
    return a;
}
__device__ __forceinline__ uint32_t sw128(uint32_t off) { return off ^ ((off >> 3) & 0x70); }

#define LDM_X4(r0, r1, r2, r3, addr) \
    asm volatile("ldmatrix.sync.aligned.m8n8.x4.shared.b16 {%0,%1,%2,%3}, [%4];" \
                 : "=r"(r0), "=r"(r1), "=r"(r2), "=r"(r3) : "r"(addr))

__device__ __forceinline__ void mma_bf16(float* c, const uint32_t* a, uint32_t b0, uint32_t b1) {
    asm volatile(
        "mma.sync.aligned.m16n8k16.row.col.f32.bf16.bf16.f32 "
        "{%0,%1,%2,%3}, {%4,%5,%6,%7}, {%8,%9}, {%0,%1,%2,%3};"
        : "+f"(c[0]), "+f"(c[1]), "+f"(c[2]), "+f"(c[3])
        : "r"(a[0]), "r"(a[1]), "r"(a[2]), "r"(a[3]), "r"(b0), "r"(b1));
}

__device__ __forceinline__ unsigned long long pack4hi(float4 v) {
    __nv_bfloat162 p0 = __floats2bfloat162_rn(v.x, v.y);
    __nv_bfloat162 p1 = __floats2bfloat162_rn(v.z, v.w);
    unsigned lo32 = *reinterpret_cast<unsigned*>(&p0);
    unsigned hi32 = *reinterpret_cast<unsigned*>(&p1);
    return ((unsigned long long)hi32 << 32) | lo32;
}

__device__ __forceinline__ float mg_from_arg(float arg) {
    float t;
    asm("ex2.approx.f32 %0, %1;" : "=f"(t) : "f"(arg));
    float t2 = t * t;
    float s1 = fmaf(t, t, t);
    float t4 = t2 * t2;
    float t8 = t4 * t4;
    float s2 = fmaf(t8, t8, t8);
    return (s1 + t4) + s2;
}

// ---------------------------------------------------------------------------
// k1a: per (b,s,g) -> Kss (49x49) fp32-exact -> g_kss. 13x13 of 4x4 tiles.
// ---------------------------------------------------------------------------
__global__ __launch_bounds__(192) void k1a_kss(const float* __restrict__ sup) {
    __shared__ float xs[52 * STR_];
    __shared__ float ssq[52];

    int bid = blockIdx.x;
    int tid = threadIdx.x;

    const float* sb = sup + (size_t)bid * 49 * 64;
    for (int idx = tid; idx < 52 * 16; idx += 192) {
        int r = idx >> 4, c4 = idx & 15;
        float4 v = make_float4(0.f, 0.f, 0.f, 0.f);
        if (r < 49) v = *(const float4*)(sb + r * 64 + c4 * 4);
        *(float4*)(xs + r * STR_ + c4 * 4) = v;
    }
    __syncthreads();

    if (tid < 52) {
        const float2* xr = (const float2*)(xs + tid * STR_);
        float a0 = 0.f, a1 = 0.f;
        #pragma unroll
        for (int c = 0; c < 32; c++) { float2 x = xr[c]; a0 = fmaf(x.x, x.x, a0); a1 = fmaf(x.y, x.y, a1); }
        ssq[tid] = NEG_L2E8 * (a0 + a1);
    }
    __syncthreads();

    if (tid < 169) {
        int it = tid / 13, jt = tid - it * 13;
        float acc[16];
        #pragma unroll
        for (int k = 0; k < 16; k++) acc[k] = 0.f;
        const float2* A  = (const float2*)(xs + it * 4 * STR_);
        const float2* Bm = (const float2*)(xs + jt * 4 * STR_);
        #pragma unroll 2
        for (int c2 = 0; c2 < 32; c2++) {
            float2 a[4], bb[4];
            #pragma unroll
            for (int k = 0; k < 4; k++) a[k]  = A[k * (STR_ / 2) + c2];
            #pragma unroll
            for (int k = 0; k < 4; k++) bb[k] = Bm[k * (STR_ / 2) + c2];
            #pragma unroll
            for (int ii = 0; ii < 4; ii++)
                #pragma unroll
                for (int jj = 0; jj < 4; jj++) {
                    acc[ii * 4 + jj] = fmaf(a[ii].x, bb[jj].x, acc[ii * 4 + jj]);
                    acc[ii * 4 + jj] = fmaf(a[ii].y, bb[jj].y, acc[ii * 4 + jj]);
                }
        }
        float* kout = g_kss + (size_t)bid * 2401;
        #pragma unroll
        for (int ii = 0; ii < 4; ii++) {
            int i = it * 4 + ii;
            if (i < 49) {
                float ai = ssq[i];
                #pragma unroll
                for (int jj = 0; jj < 4; jj++) {
                    int j = jt * 4 + jj;
                    if (j < 49) {
                        float arg = fmaf(POS_L2E4, acc[ii * 4 + jj], ai + ssq[j]);
                        kout[i * 49 + j] = mg_from_arg(arg);
                    }
                }
            }
        }
    }
}

// ---------------------------------------------------------------------------
// k1b: per (b,s,g,vchunk of 15) -> beta^T Kss beta (Kss L2-hot)
// ---------------------------------------------------------------------------
__global__ __launch_bounds__(256) void k1b_bilinear(const float* __restrict__ beta) {
    __shared__ float kss[49 * 50];
    __shared__ float betas[15 * 50];
    __shared__ float scr[735];

    int bid = blockIdx.x;
    int g = bid & 3;
    int rest = bid >> 2;
    int s = rest % NS_;  rest /= NS_;
    int vt = rest % 5;
    int b = rest / 5;
    int tid = threadIdx.x;

    int bid160 = (b * NS_ + s) * NG_ + g;
    const float* ksrc = g_kss + (size_t)bid160 * 2401;
    for (int idx = tid; idx < 2401; idx += 256) {
        int i = idx / 49, j = idx - i * 49;
        kss[i * 50 + j] = ksrc[idx];
    }
    for (int idx = tid; idx < 15 * 49; idx += 256) {
        int vv = idx / 49, j = idx - vv * 49;
        int v = vt * 15 + vv;
        size_t off = ((size_t)((b * NQ_ + v) * NS_ + s) * NG_ + g) * 49 + j;
        betas[vv * 50 + j] = beta[off];
    }
    __syncthreads();

    for (int t = tid; t < 735; t += 256) {
        int vv = t / 49, i = t - vv * 49;
        const float2* kr = (const float2*)(kss + i * 50);
        const float2* bv = (const float2*)(betas + vv * 50);
        float r0 = 0.f, r1 = 0.f;
        #pragma unroll
        for (int c = 0; c < 24; c++) {
            float2 kk = kr[c], bb = bv[c];
            r0 = fmaf(kk.x, bb.x, r0);
            r1 = fmaf(kk.y, bb.y, r1);
        }
        float r = r0 + r1 + kss[i * 50 + 48] * betas[vv * 50 + 48];
        scr[t] = betas[vv * 50 + i] * r;
    }
    __syncthreads();

    if (tid < 15) {
        float acc = 0.f;
        #pragma unroll
        for (int k = 0; k < 49; k++) acc += scr[tid * 49 + k];
        int v = vt * 15 + tid;
        g_p1[((b * NQ_ + v) * NS_ + s) * NG_ + g] = acc;
    }
}

// ---------------------------------------------------------------------------
// k2: per (b,v,g). Single-pass bf16 mma.sync m16n8k16 for all dots:
//   A[320x64] = support(245)+query(49)+pad, B[64x64] = query(49)+pad.
// Kqq diagonal set EXACTLY (kv=5, d2==0) — removes the only sharp-sensitivity
// point; off-diagonal pairs all have d2 >~ 40 where bf16 dot noise is harmless.
// Fused epilogue: folded ex2 arg -> multi-gauss -> bilinear, scr4 reduce.
// ---------------------------------------------------------------------------
__global__ __launch_bounds__(NT2_, 1) void k2_main(const float* __restrict__ sup,
                                                   const float* __restrict__ qry,
                                                   const float* __restrict__ beta,
                                                   const float* __restrict__ gamma) {
    extern __shared__ char smc[];
    uint32_t sbase = smem_u32(smc);
    float* fb    = (float*)(smc + FBASE_);
    float* rsq   = fb + F_RSQ;
    float* bet   = fb + F_BET;
    float* gam   = fb + F_GAM;
    float* scr   = fb + F_SCR;
    float* scrq  = fb + F_SCRQ;
    float* scr4  = fb + F_SCR4;
    float* scrq4 = fb + F_SCRQ4;
    float* red   = fb + F_RED;
    float* sqp   = fb + F_SQP;

    int bid = blockIdx.x;
    int g = bid & 3;
    int bv = bid >> 2;
    int b = bv / NQ_;
    int tid = threadIdx.x;
    int wid = tid >> 5;
    int lane = tid & 31;

    const float* supb = sup + (size_t)(b * (NS_ * NG_) + g) * 49 * 64;
    const float* qryb = qry + ((size_t)bv * NG_ + g) * 49 * 64;

    // ---- A tile (320 rows): bf16 pack + fp32 square partials ----
    for (int idx = tid; idx < 320 * 16; idx += NT2_) {
        int r = idx >> 4, c8 = idx & 15;
        unsigned long long hi = 0ull;
        if (r < 294) {
            float4 v;
            if (r < 245) {
                int s = r / 49, i = r - s * 49;
                v = *(const float4*)(supb + (size_t)s * (NG_ * 49 * 64) + i * 64 + c8 * 4);
            } else {
                v = *(const float4*)(qryb + (r - 245) * 64 + c8 * 4);
            }
            hi = pack4hi(v);
            sqp[r * 16 + c8] = fmaf(v.x, v.x, fmaf(v.y, v.y, fmaf(v.z, v.z, v.w * v.w)));
        }
        *(unsigned long long*)(smc + O_AHI + sw128((uint32_t)(r * 128 + c8 * 8))) = hi;
    }
    // ---- B tile (64 rows, query) ----
    for (int idx = tid; idx < 64 * 16; idx += NT2_) {
        int r = idx >> 4, c8 = idx & 15;
        unsigned long long hi = 0ull;
        if (r < 49) hi = pack4hi(*(const float4*)(qryb + r * 64 + c8 * 4));
        *(unsigned long long*)(smc + O_BHI + sw128((uint32_t)(r * 128 + c8 * 8))) = hi;
    }
    for (int idx = tid; idx < NS_ * 49; idx += NT2_) {
        int s = idx / 49, j = idx - s * 49;
        size_t off = ((size_t)(bv * NS_ + s) * NG_ + g) * 49 + j;
        bet[idx] = beta[off];
        gam[idx] = gamma[off];
    }
    __syncthreads();

    if (tid < 320) {
        float a = 0.f;
        if (tid < 294) {
            const float* p = sqp + tid * 16;
            #pragma unroll
            for (int k = 0; k < 16; k++) a += p[k];
        }
        rsq[tid] = NEG_L2E8 * a;
    }
    __syncthreads();

    if (wid < 10) {
        float Cf[2][8][4];
        #pragma unroll
        for (int mt = 0; mt < 2; mt++)
            #pragma unroll
            for (int nt = 0; nt < 8; nt++)
                #pragma unroll
                for (int e = 0; e < 4; e++) Cf[mt][nt][e] = 0.f;

        int a_row = lane & 15;
        int a_kh  = lane >> 4;
        int b_row = (lane & 7) + ((lane >> 4) << 3);
        int b_kh  = (lane >> 3) & 1;

        #pragma unroll
        for (int k = 0; k < 4; k++) {
            uint32_t ah[2][4], bh[4][4];
            #pragma unroll
            for (int mt = 0; mt < 2; mt++) {
                uint32_t off = sw128((uint32_t)((wid * 32 + mt * 16 + a_row) * 128 + k * 32 + a_kh * 16));
                LDM_X4(ah[mt][0], ah[mt][1], ah[mt][2], ah[mt][3], sbase + O_AHI + off);
            }
            #pragma unroll
            for (int np = 0; np < 4; np++) {
                uint32_t off = sw128((uint32_t)((np * 16 + b_row) * 128 + k * 32 + b_kh * 16));
                LDM_X4(bh[np][0], bh[np][1], bh[np][2], bh[np][3], sbase + O_BHI + off);
            }
            #pragma unroll
            for (int mt = 0; mt < 2; mt++)
                #pragma unroll
                for (int nt = 0; nt < 8; nt++)
                    mma_bf16(Cf[mt][nt], ah[mt], bh[nt >> 1][(nt & 1) * 2], bh[nt >> 1][(nt & 1) * 2 + 1]);
        }

        int p4 = lane & 3;
        #pragma unroll
        for (int mt = 0; mt < 2; mt++)
            #pragma unroll
            for (int hf = 0; hf < 2; hf++) {
                int r = wid * 32 + mt * 16 + (lane >> 2) + hf * 8;
                if (r < 245) {
                    float ai = rsq[r];
                    int s = r / 49;
                    const float* gs = gam + s * 49;
                    float part = 0.f;
                    #pragma unroll
                    for (int nt = 0; nt < 8; nt++)
                        #pragma unroll
                        for (int e = 0; e < 2; e++) {
                            int col = nt * 8 + 2 * p4 + e;
                            if (col < 49) {
                                float arg = fmaf(POS_L2E4, Cf[mt][nt][hf * 2 + e], ai + rsq[245 + col]);
                                part = fmaf(mg_from_arg(arg), gs[col], part);
                            }
                        }
                    scr4[r * 4 + p4] = part;
                } else if (r < 294) {
                    float ai = rsq[r];
                    int q = r - 245;
                    float pq[5] = {0.f, 0.f, 0.f, 0.f, 0.f};
                    #pragma unroll
                    for (int nt = 0; nt < 8; nt++)
                        #pragma unroll
                        for (int e = 0; e < 2; e++) {
                            int col = nt * 8 + 2 * p4 + e;
                            if (col < 49) {
                                float kv;
                                if (col == q) {
                                    kv = 5.0f;   // exact: d2(i,i) == 0
                                } else {
                                    float arg = fmaf(POS_L2E4, Cf[mt][nt][hf * 2 + e], ai + rsq[245 + col]);
                                    kv = mg_from_arg(arg);
                                }
                                #pragma unroll
                                for (int s = 0; s < 5; s++) pq[s] = fmaf(kv, gam[s * 49 + col], pq[s]);
                            }
                        }
                    #pragma unroll
                    for (int s = 0; s < 5; s++) scrq4[(s * 49 + q) * 4 + p4] = pq[s];
                }
            }
    }
    __syncthreads();

    for (int j = tid; j < 490; j += NT2_) {
        if (j < 245) {
            float v = scr4[j * 4] + scr4[j * 4 + 1] + scr4[j * 4 + 2] + scr4[j * 4 + 3];
            scr[j] = bet[j] * v;
        } else {
            int q = j - 245;   // composite s*49+qq
            float v = scrq4[q * 4] + scrq4[q * 4 + 1] + scrq4[q * 4 + 2] + scrq4[q * 4 + 3];
            scrq[q] = gam[q] * v;
        }
    }
    __syncthreads();

    if (tid < 10) {
        int s = tid % 5;
        const float* src = (tid < 5) ? (scr + s * 49) : (scrq + s * 49);
        float acc = 0.f;
        #pragma unroll
        for (int k = 0; k < 49; k++) acc += src[k];
        red[tid] = acc;
    }
    __syncthreads();

    if (tid < NS_) {
        int idx = (bv * NS_ + tid) * NG_ + g;
        g_p2[idx] = red[5 + tid] - 2.0f * red[tid];
    }
}

__global__ void k3_reduce(float* __restrict__ out) {
    int o = blockIdx.x * blockDim.x + threadIdx.x;
    if (o < B_ * NQ_ * NS_) {
        float s = 0.0f;
        #pragma unroll
        for (int g = 0; g < NG_; g++) s += g_p1[o * NG_ + g] + g_p2[o * NG_ + g];
        out[o] = 0.25f * s;
    }
}

extern "C" void kernel_launch(void* const* d_in, const int* in_sizes, int n_in,
                              void* d_out, int out_size) {
    const float* sup   = (const float*)d_in[0];
    const float* qry   = (const float*)d_in[1];
    const float* beta  = (const float*)d_in[2];
    const float* gamma = (const float*)d_in[3];
    float* out = (float*)d_out;

    static bool configured = false;
    if (!configured) {
        cudaFuncSetAttribute(k2_main, cudaFuncAttributeMaxDynamicSharedMemorySize, SM2_BYTES);
        configured = true;
    }

    k1a_kss<<<B_ * NS_ * NG_, 192>>>(sup);
    k1b_bilinear<<<B_ * NS_ * NG_ * 5, 256>>>(beta);
    k2_main<<<B_ * NQ_ * NG_, NT2_, SM2_BYTES>>>(sup, qry, beta, gamma);
    k3_reduce<<<(B_ * NQ_ * NS_ + 255) / 256, 256>>>(out);
}

// round 16
// speedup vs baseline: 2.0994x; 1.4849x over previous
#include <cuda_runtime.h>
#include <cuda_bf16.h>
#include <cstdint>

#define B_   8
#define NQ_  75
#define NS_  5
#define NG_  4
#define NF_  49
#define C_   64

#define STR_  68
#define NT2_  320

#define NEG_L2E8  (-0.18033688011112042f)
#define POS_L2E4  ( 0.36067376022224084f)

// ---- k2 smem layout (bytes / floats) ----
#define O_AHI   0                 // 320*128 bf16 tile
#define O_BHI   40960             // 64*128
#define FBASE_  49152
#define F_RSQ   0                 // 320
#define F_BET   320               // 248
#define F_GAM   568               // 248
#define F_SCR   816               // 248
#define F_SCRQ  1064              // 248
#define F_SCR4  1312              // 980
#define F_SCRQ4 2292              // 980
#define F_RED   3272              // 16
#define F_SQP   3288              // 320*16
#define SM2_BYTES (FBASE_ + (F_SQP + 5120) * 4)

__device__ float g_p1[B_ * NQ_ * NS_ * NG_];
__device__ float g_p2[B_ * NQ_ * NS_ * NG_];
__device__ float g_kss[B_ * NS_ * NG_ * NF_ * NF_];

__device__ __forceinline__ uint32_t smem_u32(const void* p) {
    uint32_t a;
    asm("{ .reg .u64 t; cvta.to.shared.u64 t, %1; cvt.u32.u64 %0, t; }" : "=r"(a) : "l"(p));
    return a;
}
__device__ __forceinline__ uint32_t sw128(uint32_t off) { return off ^ ((off >> 3) & 0x70); }

#define LDM_X4(r0, r1, r2, r3, addr) \
    asm volatile("ldmatrix.sync.aligned.m8n8.x4.shared.b16 {%0,%1,%2,%3}, [%4];" \
                 : "=r"(r0), "=r"(r1), "=r"(r2), "=r"(r3) : "r"(addr))

__device__ __forceinline__ void mma_bf16(float* c, const uint32_t* a, uint32_t b0, uint32_t b1) {
    asm volatile(
        "mma.sync.aligned.m16n8k16.row.col.f32.bf16.bf16.f32 "
        "{%0,%1,%2,%3}, {%4,%5,%6,%7}, {%8,%9}, {%0,%1,%2,%3};"
        : "+f"(c[0]), "+f"(c[1]), "+f"(c[2]), "+f"(c[3])
        : "r"(a[0]), "r"(a[1]), "r"(a[2]), "r"(a[3]), "r"(b0), "r"(b1));
}

__device__ __forceinline__ unsigned long long pack4hi(float4 v) {
    __nv_bfloat162 p0 = __floats2bfloat162_rn(v.x, v.y);
    __nv_bfloat162 p1 = __floats2bfloat162_rn(v.z, v.w);
    unsigned lo32 = *reinterpret_cast<unsigned*>(&p0);
    unsigned hi32 = *reinterpret_cast<unsigned*>(&p1);
    return ((unsigned long long)hi32 << 32) | lo32;
}

__device__ __forceinline__ float mg_from_arg(float arg) {
    float t;
    asm("ex2.approx.f32 %0, %1;" : "=f"(t) : "f"(arg));
    float t2 = t * t;
    float s1 = fmaf(t, t, t);
    float t4 = t2 * t2;
    float t8 = t4 * t4;
    float s2 = fmaf(t8, t8, t8);
    return (s1 + t4) + s2;
}

// ---------------------------------------------------------------------------
// k1a: per (b,s,g) -> Kss (49x49) fp32-exact -> g_kss. 13x13 of 4x4 tiles.
// ---------------------------------------------------------------------------
__global__ __launch_bounds__(192) void k1a_kss(const float* __restrict__ sup) {
    __shared__ float xs[52 * STR_];
    __shared__ float ssq[52];

    int bid = blockIdx.x;
    int tid = threadIdx.x;

    const float* sb = sup + (size_t)bid * 49 * 64;
    for (int idx = tid; idx < 52 * 16; idx += 192) {
        int r = idx >> 4, c4 = idx & 15;
        float4 v = make_float4(0.f, 0.f, 0.f, 0.f);
        if (r < 49) v = *(const float4*)(sb + r * 64 + c4 * 4);
        *(float4*)(xs + r * STR_ + c4 * 4) = v;
    }
    __syncthreads();

    if (tid < 52) {
        const float2* xr = (const float2*)(xs + tid * STR_);
        float a0 = 0.f, a1 = 0.f;
        #pragma unroll
        for (int c = 0; c < 32; c++) { float2 x = xr[c]; a0 = fmaf(x.x, x.x, a0); a1 = fmaf(x.y, x.y, a1); }
        ssq[tid] = NEG_L2E8 * (a0 + a1);
    }
    __syncthreads();

    if (tid < 169) {
        int it = tid / 13, jt = tid - it * 13;
        float acc[16];
        #pragma unroll
        for (int k = 0; k < 16; k++) acc[k] = 0.f;
        const float2* A  = (const float2*)(xs + it * 4 * STR_);
        const float2* Bm = (const float2*)(xs + jt * 4 * STR_);
        #pragma unroll 2
        for (int c2 = 0; c2 < 32; c2++) {
            float2 a[4], bb[4];
            #pragma unroll
            for (int k = 0; k < 4; k++) a[k]  = A[k * (STR_ / 2) + c2];
            #pragma unroll
            for (int k = 0; k < 4; k++) bb[k] = Bm[k * (STR_ / 2) + c2];
            #pragma unroll
            for (int ii = 0; ii < 4; ii++)
                #pragma unroll
                for (int jj = 0; jj < 4; jj++) {
                    acc[ii * 4 + jj] = fmaf(a[ii].x, bb[jj].x, acc[ii * 4 + jj]);
                    acc[ii * 4 + jj] = fmaf(a[ii].y, bb[jj].y, acc[ii * 4 + jj]);
                }
        }
        float* kout = g_kss + (size_t)bid * 2401;
        #pragma unroll
        for (int ii = 0; ii < 4; ii++) {
            int i = it * 4 + ii;
            if (i < 49) {
                float ai = ssq[i];
                #pragma unroll
                for (int jj = 0; jj < 4; jj++) {
                    int j = jt * 4 + jj;
                    if (j < 49) {
                        float arg = fmaf(POS_L2E4, acc[ii * 4 + jj], ai + ssq[j]);
                        kout[i * 49 + j] = mg_from_arg(arg);
                    }
                }
            }
        }
    }
}

// ---------------------------------------------------------------------------
// k1b: per (b,s,g,vchunk of 15) -> beta^T Kss beta (Kss L2-hot)
// ---------------------------------------------------------------------------
__global__ __launch_bounds__(256) void k1b_bilinear(const float* __restrict__ beta) {
    __shared__ float kss[49 * 50];
    __shared__ float betas[15 * 50];
    __shared__ float scr[735];

    int bid = blockIdx.x;
    int g = bid & 3;
    int rest = bid >> 2;
    int s = rest % NS_;  rest /= NS_;
    int vt = rest % 5;
    int b = rest / 5;
    int tid = threadIdx.x;

    int bid160 = (b * NS_ + s) * NG_ + g;
    const float* ksrc = g_kss + (size_t)bid160 * 2401;
    for (int idx = tid; idx < 2401; idx += 256) {
        int i = idx / 49, j = idx - i * 49;
        kss[i * 50 + j] = ksrc[idx];
    }
    for (int idx = tid; idx < 15 * 49; idx += 256) {
        int vv = idx / 49, j = idx - vv * 49;
        int v = vt * 15 + vv;
        size_t off = ((size_t)((b * NQ_ + v) * NS_ + s) * NG_ + g) * 49 + j;
        betas[vv * 50 + j] = beta[off];
    }
    __syncthreads();

    for (int t = tid; t < 735; t += 256) {
        int vv = t / 49, i = t - vv * 49;
        const float2* kr = (const float2*)(kss + i * 50);
        const float2* bv = (const float2*)(betas + vv * 50);
        float r0 = 0.f, r1 = 0.f;
        #pragma unroll
        for (int c = 0; c < 24; c++) {
            float2 kk = kr[c], bb = bv[c];
            r0 = fmaf(kk.x, bb.x, r0);
            r1 = fmaf(kk.y, bb.y, r1);
        }
        float r = r0 + r1 + kss[i * 50 + 48] * betas[vv * 50 + 48];
        scr[t] = betas[vv * 50 + i] * r;
    }
    __syncthreads();

    if (tid < 15) {
        float acc = 0.f;
        #pragma unroll
        for (int k = 0; k < 49; k++) acc += scr[tid * 49 + k];
        int v = vt * 15 + tid;
        g_p1[((b * NQ_ + v) * NS_ + s) * NG_ + g] = acc;
    }
}

// ---------------------------------------------------------------------------
// k2: per (b,v,g). bf16 mma.sync dots, exact Kqq diagonal, fused epilogue.
// 320 threads / 10 warps (1 warp per 32-row M-tile), 2 CTAs/SM target.
// ---------------------------------------------------------------------------
__global__ __launch_bounds__(NT2_, 2) void k2_main(const float* __restrict__ sup,
                                                   const float* __restrict__ qry,
                                                   const float* __restrict__ beta,
                                                   const float* __restrict__ gamma) {
    extern __shared__ char smc[];
    uint32_t sbase = smem_u32(smc);
    float* fb    = (float*)(smc + FBASE_);
    float* rsq   = fb + F_RSQ;
    float* bet   = fb + F_BET;
    float* gam   = fb + F_GAM;
    float* scr   = fb + F_SCR;
    float* scrq  = fb + F_SCRQ;
    float* scr4  = fb + F_SCR4;
    float* scrq4 = fb + F_SCRQ4;
    float* red   = fb + F_RED;
    float* sqp   = fb + F_SQP;

    int bid = blockIdx.x;
    int g = bid & 3;
    int bv = bid >> 2;
    int b = bv / NQ_;
    int tid = threadIdx.x;
    int wid = tid >> 5;
    int lane = tid & 31;

    const float* supb = sup + (size_t)(b * (NS_ * NG_) + g) * 49 * 64;
    const float* qryb = qry + ((size_t)bv * NG_ + g) * 49 * 64;

    for (int idx = tid; idx < 320 * 16; idx += NT2_) {
        int r = idx >> 4, c8 = idx & 15;
        unsigned long long hi = 0ull;
        if (r < 294) {
            float4 v;
            if (r < 245) {
                int s = r / 49, i = r - s * 49;
                v = *(const float4*)(supb + (size_t)s * (NG_ * 49 * 64) + i * 64 + c8 * 4);
            } else {
                v = *(const float4*)(qryb + (r - 245) * 64 + c8 * 4);
            }
            hi = pack4hi(v);
            sqp[r * 16 + c8] = fmaf(v.x, v.x, fmaf(v.y, v.y, fmaf(v.z, v.z, v.w * v.w)));
        }
        *(unsigned long long*)(smc + O_AHI + sw128((uint32_t)(r * 128 + c8 * 8))) = hi;
    }
    for (int idx = tid; idx < 64 * 16; idx += NT2_) {
        int r = idx >> 4, c8 = idx & 15;
        unsigned long long hi = 0ull;
        if (r < 49) hi = pack4hi(*(const float4*)(qryb + r * 64 + c8 * 4));
        *(unsigned long long*)(smc + O_BHI + sw128((uint32_t)(r * 128 + c8 * 8))) = hi;
    }
    for (int idx = tid; idx < NS_ * 49; idx += NT2_) {
        int s = idx / 49, j = idx - s * 49;
        size_t off = ((size_t)(bv * NS_ + s) * NG_ + g) * 49 + j;
        bet[idx] = beta[off];
        gam[idx] = gamma[off];
    }
    __syncthreads();

    if (tid < 320) {
        float a = 0.f;
        if (tid < 294) {
            const float* p = sqp + tid * 16;
            #pragma unroll
            for (int k = 0; k < 16; k++) a += p[k];
        }
        rsq[tid] = NEG_L2E8 * a;
    }
    __syncthreads();

    {
        float Cf[2][8][4];
        #pragma unroll
        for (int mt = 0; mt < 2; mt++)
            #pragma unroll
            for (int nt = 0; nt < 8; nt++)
                #pragma unroll
                for (int e = 0; e < 4; e++) Cf[mt][nt][e] = 0.f;

        int a_row = lane & 15;
        int a_kh  = lane >> 4;
        int b_row = (lane & 7) + ((lane >> 4) << 3);
        int b_kh  = (lane >> 3) & 1;

        #pragma unroll
        for (int k = 0; k < 4; k++) {
            uint32_t bh[4][4];
            #pragma unroll
            for (int np = 0; np < 4; np++) {
                uint32_t off = sw128((uint32_t)((np * 16 + b_row) * 128 + k * 32 + b_kh * 16));
                LDM_X4(bh[np][0], bh[np][1], bh[np][2], bh[np][3], sbase + O_BHI + off);
            }
            #pragma unroll
            for (int mt = 0; mt < 2; mt++) {
                uint32_t ah[4];
                uint32_t off = sw128((uint32_t)((wid * 32 + mt * 16 + a_row) * 128 + k * 32 + a_kh * 16));
                LDM_X4(ah[0], ah[1], ah[2], ah[3], sbase + O_AHI + off);
                #pragma unroll
                for (int nt = 0; nt < 8; nt++)
                    mma_bf16(Cf[mt][nt], ah, bh[nt >> 1][(nt & 1) * 2], bh[nt >> 1][(nt & 1) * 2 + 1]);
            }
        }

        int p4 = lane & 3;
        #pragma unroll
        for (int mt = 0; mt < 2; mt++)
            #pragma unroll
            for (int hf = 0; hf < 2; hf++) {
                int r = wid * 32 + mt * 16 + (lane >> 2) + hf * 8;
                if (r < 245) {
                    float ai = rsq[r];
                    int s = r / 49;
                    const float* gs = gam + s * 49;
                    float part = 0.f;
                    #pragma unroll
                    for (int nt = 0; nt < 8; nt++)
                        #pragma unroll
                        for (int e = 0; e < 2; e++) {
                            int col = nt * 8 + 2 * p4 + e;
                            if (col < 49) {
                                float arg = fmaf(POS_L2E4, Cf[mt][nt][hf * 2 + e], ai + rsq[245 + col]);
                                part = fmaf(mg_from_arg(arg), gs[col], part);
                            }
                        }
                    scr4[r * 4 + p4] = part;
                } else if (r < 294) {
                    float ai = rsq[r];
                    int q = r - 245;
                    float pq[5] = {0.f, 0.f, 0.f, 0.f, 0.f};
                    #pragma unroll
                    for (int nt = 0; nt < 8; nt++)
                        #pragma unroll
                        for (int e = 0; e < 2; e++) {
                            int col = nt * 8 + 2 * p4 + e;
                            if (col < 49) {
                                float kv;
                                if (col == q) {
                                    kv = 5.0f;   // exact: d2(i,i) == 0
                                } else {
                                    float arg = fmaf(POS_L2E4, Cf[mt][nt][hf * 2 + e], ai + rsq[245 + col]);
                                    kv = mg_from_arg(arg);
                                }
                                #pragma unroll
                                for (int s = 0; s < 5; s++) pq[s] = fmaf(kv, gam[s * 49 + col], pq[s]);
                            }
                        }
                    #pragma unroll
                    for (int s = 0; s < 5; s++) scrq4[(s * 49 + q) * 4 + p4] = pq[s];
                }
            }
    }
    __syncthreads();

    for (int j = tid; j < 490; j += NT2_) {
        if (j < 245) {
            float v = scr4[j * 4] + scr4[j * 4 + 1] + scr4[j * 4 + 2] + scr4[j * 4 + 3];
            scr[j] = bet[j] * v;
        } else {
            int q = j - 245;
            float v = scrq4[q * 4] + scrq4[q * 4 + 1] + scrq4[q * 4 + 2] + scrq4[q * 4 + 3];
            scrq[q] = gam[q] * v;
        }
    }
    __syncthreads();

    if (tid < 10) {
        int s = tid % 5;
        const float* src = (tid < 5) ? (scr + s * 49) : (scrq + s * 49);
        float acc = 0.f;
        #pragma unroll
        for (int k = 0; k < 49; k++) acc += src[k];
        red[tid] = acc;
    }
    __syncthreads();

    if (tid < NS_) {
        int idx = (bv * NS_ + tid) * NG_ + g;
        g_p2[idx] = red[5 + tid] - 2.0f * red[tid];
    }
}

__global__ void k3_reduce(float* __restrict__ out) {
    int o = blockIdx.x * blockDim.x + threadIdx.x;
    if (o < B_ * NQ_ * NS_) {
        float s = 0.0f;
        #pragma unroll
        for (int g = 0; g < NG_; g++) s += g_p1[o * NG_ + g] + g_p2[o * NG_ + g];
        out[o] = 0.25f * s;
    }
}

extern "C" void kernel_launch(void* const* d_in, const int* in_sizes, int n_in,
                              void* d_out, int out_size) {
    const float* sup   = (const float*)d_in[0];
    const float* qry   = (const float*)d_in[1];
    const float* beta  = (const float*)d_in[2];
    const float* gamma = (const float*)d_in[3];
    float* out = (float*)d_out;

    static bool configured = false;
    if (!configured) {
        cudaFuncSetAttribute(k2_main, cudaFuncAttributeMaxDynamicSharedMemorySize, SM2_BYTES);
        configured = true;
    }

    // Order: k1a, k2, k1b, k3 — k1b depends only on k1a (same stream keeps
    // the dependency); puts k2 at launch index 1 mod 4 so ncu's -s 5 -c 1
    // window lands on a k2 instance for next round's diagnosis.
    k1a_kss<<<B_ * NS_ * NG_, 192>>>(sup);
    k2_main<<<B_ * NQ_ * NG_, NT2_, SM2_BYTES>>>(sup, qry, beta, gamma);
    k1b_bilinear<<<B_ * NS_ * NG_ * 5, 256>>>(beta);
    k3_reduce<<<(B_ * NQ_ * NS_ + 255) / 256, 256>>>(out);
}

// round 17
// speedup vs baseline: 2.1806x; 1.0387x over previous
#include <cuda_runtime.h>
#include <cuda_bf16.h>
#include <cstdint>

#define B_   8
#define NQ_  75
#define NS_  5
#define NG_  4
#define NF_  49
#define C_   64

#define STR_  68
#define NT2_  320

#define NEG_L2E8  (-0.18033688011112042f)
#define POS_L2E4  ( 0.36067376022224084f)

// ---- k2 smem layout (bytes / floats) ----
#define O_AHI   0                 // 320*128 bf16 tile
#define O_BHI   40960             // 64*128
#define FBASE_  49152
#define F_RSQ   0                 // 320
#define F_BET   320               // 248
#define F_GAM   568               // 248
#define F_SCR   816               // 248
#define F_SCRQ  1064              // 248
#define F_SCR4  1312              // 980
#define F_SCRQ4 2292              // 980
#define F_RED   3272              // 16
#define F_SQP   3288              // 320*16
#define SM2_BYTES (FBASE_ + (F_SQP + 5120) * 4)

__device__ float g_p1[B_ * NQ_ * NS_ * NG_];
__device__ float g_p2[B_ * NQ_ * NS_ * NG_];
__device__ float g_kss[B_ * NS_ * NG_ * NF_ * NF_];

__device__ __forceinline__ uint32_t smem_u32(const void* p) {
    uint32_t a;
    asm("{ .reg .u64 t; cvta.to.shared.u64 t, %1; cvt.u32.u64 %0, t; }" : "=r"(a) : "l"(p));
    return a;
}
__device__ __forceinline__ uint32_t sw128(uint32_t off) { return off ^ ((off >> 3) & 0x70); }

#define LDM_X4(r0, r1, r2, r3, addr) \
    asm volatile("ldmatrix.sync.aligned.m8n8.x4.shared.b16 {%0,%1,%2,%3}, [%4];" \
                 : "=r"(r0), "=r"(r1), "=r"(r2), "=r"(r3) : "r"(addr))

__device__ __forceinline__ void mma_bf16(float* c, const uint32_t* a, uint32_t b0, uint32_t b1) {
    asm volatile(
        "mma.sync.aligned.m16n8k16.row.col.f32.bf16.bf16.f32 "
        "{%0,%1,%2,%3}, {%4,%5,%6,%7}, {%8,%9}, {%0,%1,%2,%3};"
        : "+f"(c[0]), "+f"(c[1]), "+f"(c[2]), "+f"(c[3])
        : "r"(a[0]), "r"(a[1]), "r"(a[2]), "r"(a[3]), "r"(b0), "r"(b1));
}

__device__ __forceinline__ unsigned long long pack4hi(float4 v) {
    __nv_bfloat162 p0 = __floats2bfloat162_rn(v.x, v.y);
    __nv_bfloat162 p1 = __floats2bfloat162_rn(v.z, v.w);
    unsigned lo32 = *reinterpret_cast<unsigned*>(&p0);
    unsigned hi32 = *reinterpret_cast<unsigned*>(&p1);
    return ((unsigned long long)hi32 << 32) | lo32;
}

__device__ __forceinline__ float mg_from_arg(float arg) {
    float t;
    asm("ex2.approx.f32 %0, %1;" : "=f"(t) : "f"(arg));
    float t2 = t * t;
    float s1 = fmaf(t, t, t);
    float t4 = t2 * t2;
    float t8 = t4 * t4;
    float s2 = fmaf(t8, t8, t8);
    return (s1 + t4) + s2;
}

// ---------------------------------------------------------------------------
// k1a: per (b,s,g) -> Kss (49x49) fp32-exact -> g_kss. 13x13 of 4x4 tiles.
// ---------------------------------------------------------------------------
__global__ __launch_bounds__(192) void k1a_kss(const float* __restrict__ sup) {
    __shared__ float xs[52 * STR_];
    __shared__ float ssq[52];

    int bid = blockIdx.x;
    int tid = threadIdx.x;

    const float* sb = sup + (size_t)bid * 49 * 64;
    for (int idx = tid; idx < 52 * 16; idx += 192) {
        int r = idx >> 4, c4 = idx & 15;
        float4 v = make_float4(0.f, 0.f, 0.f, 0.f);
        if (r < 49) v = *(const float4*)(sb + r * 64 + c4 * 4);
        *(float4*)(xs + r * STR_ + c4 * 4) = v;
    }
    __syncthreads();

    if (tid < 52) {
        const float2* xr = (const float2*)(xs + tid * STR_);
        float a0 = 0.f, a1 = 0.f;
        #pragma unroll
        for (int c = 0; c < 32; c++) { float2 x = xr[c]; a0 = fmaf(x.x, x.x, a0); a1 = fmaf(x.y, x.y, a1); }
        ssq[tid] = NEG_L2E8 * (a0 + a1);
    }
    __syncthreads();

    if (tid < 169) {
        int it = tid / 13, jt = tid - it * 13;
        float acc[16];
        #pragma unroll
        for (int k = 0; k < 16; k++) acc[k] = 0.f;
        const float2* A  = (const float2*)(xs + it * 4 * STR_);
        const float2* Bm = (const float2*)(xs + jt * 4 * STR_);
        #pragma unroll 2
        for (int c2 = 0; c2 < 32; c2++) {
            float2 a[4], bb[4];
            #pragma unroll
            for (int k = 0; k < 4; k++) a[k]  = A[k * (STR_ / 2) + c2];
            #pragma unroll
            for (int k = 0; k < 4; k++) bb[k] = Bm[k * (STR_ / 2) + c2];
            #pragma unroll
            for (int ii = 0; ii < 4; ii++)
                #pragma unroll
                for (int jj = 0; jj < 4; jj++) {
                    acc[ii * 4 + jj] = fmaf(a[ii].x, bb[jj].x, acc[ii * 4 + jj]);
                    acc[ii * 4 + jj] = fmaf(a[ii].y, bb[jj].y, acc[ii * 4 + jj]);
                }
        }
        float* kout = g_kss + (size_t)bid * 2401;
        #pragma unroll
        for (int ii = 0; ii < 4; ii++) {
            int i = it * 4 + ii;
            if (i < 49) {
                float ai = ssq[i];
                #pragma unroll
                for (int jj = 0; jj < 4; jj++) {
                    int j = jt * 4 + jj;
                    if (j < 49) {
                        float arg = fmaf(POS_L2E4, acc[ii * 4 + jj], ai + ssq[j]);
                        kout[i * 49 + j] = mg_from_arg(arg);
                    }
                }
            }
        }
    }
}

// ---------------------------------------------------------------------------
// k1b: per (b,s,g,vchunk of 15) -> beta^T Kss beta (Kss L2-hot)
// ---------------------------------------------------------------------------
__global__ __launch_bounds__(256) void k1b_bilinear(const float* __restrict__ beta) {
    __shared__ float kss[49 * 50];
    __shared__ float betas[15 * 50];
    __shared__ float scr[735];

    int bid = blockIdx.x;
    int g = bid & 3;
    int rest = bid >> 2;
    int s = rest % NS_;  rest /= NS_;
    int vt = rest % 5;
    int b = rest / 5;
    int tid = threadIdx.x;

    int bid160 = (b * NS_ + s) * NG_ + g;
    const float* ksrc = g_kss + (size_t)bid160 * 2401;
    for (int idx = tid; idx < 2401; idx += 256) {
        int i = idx / 49, j = idx - i * 49;
        kss[i * 50 + j] = ksrc[idx];
    }
    for (int idx = tid; idx < 15 * 49; idx += 256) {
        int vv = idx / 49, j = idx - vv * 49;
        int v = vt * 15 + vv;
        size_t off = ((size_t)((b * NQ_ + v) * NS_ + s) * NG_ + g) * 49 + j;
        betas[vv * 50 + j] = beta[off];
    }
    __syncthreads();

    for (int t = tid; t < 735; t += 256) {
        int vv = t / 49, i = t - vv * 49;
        const float2* kr = (const float2*)(kss + i * 50);
        const float2* bv = (const float2*)(betas + vv * 50);
        float r0 = 0.f, r1 = 0.f;
        #pragma unroll
        for (int c = 0; c < 24; c++) {
            float2 kk = kr[c], bb = bv[c];
            r0 = fmaf(kk.x, bb.x, r0);
            r1 = fmaf(kk.y, bb.y, r1);
        }
        float r = r0 + r1 + kss[i * 50 + 48] * betas[vv * 50 + 48];
        scr[t] = betas[vv * 50 + i] * r;
    }
    __syncthreads();

    if (tid < 15) {
        float acc = 0.f;
        #pragma unroll
        for (int k = 0; k < 49; k++) acc += scr[tid * 49 + k];
        int v = vt * 15 + tid;
        g_p1[((b * NQ_ + v) * NS_ + s) * NG_ + g] = acc;
    }
}

// ---------------------------------------------------------------------------
// k2: per (b,v,g). bf16 mma.sync dots, exact Kqq diagonal, fused epilogue.
// 320 threads / 10 warps, 2 CTAs/SM. (R16-identical)
// ---------------------------------------------------------------------------
__global__ __launch_bounds__(NT2_, 2) void k2_main(const float* __restrict__ sup,
                                                   const float* __restrict__ qry,
                                                   const float* __restrict__ beta,
                                                   const float* __restrict__ gamma) {
    extern __shared__ char smc[];
    uint32_t sbase = smem_u32(smc);
    float* fb    = (float*)(smc + FBASE_);
    float* rsq   = fb + F_RSQ;
    float* bet   = fb + F_BET;
    float* gam   = fb + F_GAM;
    float* scr   = fb + F_SCR;
    float* scrq  = fb + F_SCRQ;
    float* scr4  = fb + F_SCR4;
    float* scrq4 = fb + F_SCRQ4;
    float* red   = fb + F_RED;
    float* sqp   = fb + F_SQP;

    int bid = blockIdx.x;
    int g = bid & 3;
    int bv = bid >> 2;
    int b = bv / NQ_;
    int tid = threadIdx.x;
    int wid = tid >> 5;
    int lane = tid & 31;

    const float* supb = sup + (size_t)(b * (NS_ * NG_) + g) * 49 * 64;
    const float* qryb = qry + ((size_t)bv * NG_ + g) * 49 * 64;

    for (int idx = tid; idx < 320 * 16; idx += NT2_) {
        int r = idx >> 4, c8 = idx & 15;
        unsigned long long hi = 0ull;
        if (r < 294) {
            float4 v;
            if (r < 245) {
                int s = r / 49, i = r - s * 49;
                v = *(const float4*)(supb + (size_t)s * (NG_ * 49 * 64) + i * 64 + c8 * 4);
            } else {
                v = *(const float4*)(qryb + (r - 245) * 64 + c8 * 4);
            }
            hi = pack4hi(v);
            sqp[r * 16 + c8] = fmaf(v.x, v.x, fmaf(v.y, v.y, fmaf(v.z, v.z, v.w * v.w)));
        }
        *(unsigned long long*)(smc + O_AHI + sw128((uint32_t)(r * 128 + c8 * 8))) = hi;
    }
    for (int idx = tid; idx < 64 * 16; idx += NT2_) {
        int r = idx >> 4, c8 = idx & 15;
        unsigned long long hi = 0ull;
        if (r < 49) hi = pack4hi(*(const float4*)(qryb + r * 64 + c8 * 4));
        *(unsigned long long*)(smc + O_BHI + sw128((uint32_t)(r * 128 + c8 * 8))) = hi;
    }
    for (int idx = tid; idx < NS_ * 49; idx += NT2_) {
        int s = idx / 49, j = idx - s * 49;
        size_t off = ((size_t)(bv * NS_ + s) * NG_ + g) * 49 + j;
        bet[idx] = beta[off];
        gam[idx] = gamma[off];
    }
    __syncthreads();

    if (tid < 320) {
        float a = 0.f;
        if (tid < 294) {
            const float* p = sqp + tid * 16;
            #pragma unroll
            for (int k = 0; k < 16; k++) a += p[k];
        }
        rsq[tid] = NEG_L2E8 * a;
    }
    __syncthreads();

    {
        float Cf[2][8][4];
        #pragma unroll
        for (int mt = 0; mt < 2; mt++)
            #pragma unroll
            for (int nt = 0; nt < 8; nt++)
                #pragma unroll
                for (int e = 0; e < 4; e++) Cf[mt][nt][e] = 0.f;

        int a_row = lane & 15;
        int a_kh  = lane >> 4;
        int b_row = (lane & 7) + ((lane >> 4) << 3);
        int b_kh  = (lane >> 3) & 1;

        #pragma unroll
        for (int k = 0; k < 4; k++) {
            uint32_t bh[4][4];
            #pragma unroll
            for (int np = 0; np < 4; np++) {
                uint32_t off = sw128((uint32_t)((np * 16 + b_row) * 128 + k * 32 + b_kh * 16));
                LDM_X4(bh[np][0], bh[np][1], bh[np][2], bh[np][3], sbase + O_BHI + off);
            }
            #pragma unroll
            for (int mt = 0; mt < 2; mt++) {
                uint32_t ah[4];
                uint32_t off = sw128((uint32_t)((wid * 32 + mt * 16 + a_row) * 128 + k * 32 + a_kh * 16));
                LDM_X4(ah[0], ah[1], ah[2], ah[3], sbase + O_AHI + off);
                #pragma unroll
                for (int nt = 0; nt < 8; nt++)
                    mma_bf16(Cf[mt][nt], ah, bh[nt >> 1][(nt & 1) * 2], bh[nt >> 1][(nt & 1) * 2 + 1]);
            }
        }

        int p4 = lane & 3;
        #pragma unroll
        for (int mt = 0; mt < 2; mt++)
            #pragma unroll
            for (int hf = 0; hf < 2; hf++) {
                int r = wid * 32 + mt * 16 + (lane >> 2) + hf * 8;
                if (r < 245) {
                    float ai = rsq[r];
                    int s = r / 49;
                    const float* gs = gam + s * 49;
                    float part = 0.f;
                    #pragma unroll
                    for (int nt = 0; nt < 8; nt++)
                        #pragma unroll
                        for (int e = 0; e < 2; e++) {
                            int col = nt * 8 + 2 * p4 + e;
                            if (col < 49) {
                                float arg = fmaf(POS_L2E4, Cf[mt][nt][hf * 2 + e], ai + rsq[245 + col]);
                                part = fmaf(mg_from_arg(arg), gs[col], part);
                            }
                        }
                    scr4[r * 4 + p4] = part;
                } else if (r < 294) {
                    float ai = rsq[r];
                    int q = r - 245;
                    float pq[5] = {0.f, 0.f, 0.f, 0.f, 0.f};
                    #pragma unroll
                    for (int nt = 0; nt < 8; nt++)
                        #pragma unroll
                        for (int e = 0; e < 2; e++) {
                            int col = nt * 8 + 2 * p4 + e;
                            if (col < 49) {
                                float kv;
                                if (col == q) {
                                    kv = 5.0f;   // exact: d2(i,i) == 0
                                } else {
                                    float arg = fmaf(POS_L2E4, Cf[mt][nt][hf * 2 + e], ai + rsq[245 + col]);
                                    kv = mg_from_arg(arg);
                                }
                                #pragma unroll
                                for (int s = 0; s < 5; s++) pq[s] = fmaf(kv, gam[s * 49 + col], pq[s]);
                            }
                        }
                    #pragma unroll
                    for (int s = 0; s < 5; s++) scrq4[(s * 49 + q) * 4 + p4] = pq[s];
                }
            }
    }
    __syncthreads();

    for (int j = tid; j < 490; j += NT2_) {
        if (j < 245) {
            float v = scr4[j * 4] + scr4[j * 4 + 1] + scr4[j * 4 + 2] + scr4[j * 4 + 3];
            scr[j] = bet[j] * v;
        } else {
            int q = j - 245;
            float v = scrq4[q * 4] + scrq4[q * 4 + 1] + scrq4[q * 4 + 2] + scrq4[q * 4 + 3];
            scrq[q] = gam[q] * v;
        }
    }
    __syncthreads();

    if (tid < 10) {
        int s = tid % 5;
        const float* src = (tid < 5) ? (scr + s * 49) : (scrq + s * 49);
        float acc = 0.f;
        #pragma unroll
        for (int k = 0; k < 49; k++) acc += src[k];
        red[tid] = acc;
    }
    __syncthreads();

    if (tid < NS_) {
        int idx = (bv * NS_ + tid) * NG_ + g;
        g_p2[idx] = red[5 + tid] - 2.0f * red[tid];
    }
}

__global__ void k3_reduce(float* __restrict__ out) {
    int o = blockIdx.x * blockDim.x + threadIdx.x;
    if (o < B_ * NQ_ * NS_) {
        float s = 0.0f;
        #pragma unroll
        for (int g = 0; g < NG_; g++) s += g_p1[o * NG_ + g] + g_p2[o * NG_ + g];
        out[o] = 0.25f * s;
    }
}

extern "C" void kernel_launch(void* const* d_in, const int* in_sizes, int n_in,
                              void* d_out, int out_size) {
    const float* sup   = (const float*)d_in[0];
    const float* qry   = (const float*)d_in[1];
    const float* beta  = (const float*)d_in[2];
    const float* gamma = (const float*)d_in[3];
    float* out = (float*)d_out;

    static cudaStream_t s2 = nullptr;
    static cudaEvent_t evA = nullptr, evB = nullptr;
    static bool configured = false;
    if (!configured) {
        cudaFuncSetAttribute(k2_main, cudaFuncAttributeMaxDynamicSharedMemorySize, SM2_BYTES);
        cudaStreamCreateWithFlags(&s2, cudaStreamNonBlocking);
        cudaEventCreateWithFlags(&evA, cudaEventDisableTiming);
        cudaEventCreateWithFlags(&evB, cudaEventDisableTiming);
        configured = true;
    }

    // Fork: FFMA-pipe k1 chain overlaps tensor-pipe k2 (k2 no longer
    // saturates the FMA issue slots; R9's failure condition is gone).
    cudaEventRecord(evA, 0);
    cudaStreamWaitEvent(s2, evA, 0);
    k1a_kss<<<B_ * NS_ * NG_, 192, 0, s2>>>(sup);
    k1b_bilinear<<<B_ * NS_ * NG_ * 5, 256, 0, s2>>>(beta);
    cudaEventRecord(evB, s2);

    k2_main<<<B_ * NQ_ * NG_, NT2_, SM2_BYTES>>>(sup, qry, beta, gamma);

    cudaStreamWaitEvent(0, evB, 0);
    k3_reduce<<<(B_ * NQ_ * NS_ + 255) / 256, 256>>>(out);
}